// round 6
// baseline (speedup 1.0000x reference)
#include <cuda_runtime.h>
#include <cuda_fp16.h>
#include <cstdint>

#define NN   8192
#define FIN  256
#define FOUT 128

// ---------------- device scratch ----------------
__device__ __align__(16) __half g_WhT[FOUT * NN];      // 2 MB, [f][j], fp16
__device__ __align__(16) float g_num[4 * NN * FOUT];   // 16 MB split-j partials
__device__ float g_den[4 * NN];
__device__ float g_s1[NN];
__device__ float g_s2[NN];

// ---------------- helpers ----------------
__device__ __forceinline__ uint32_t smem_u32(const void* p) {
    uint32_t a;
    asm("{ .reg .u64 t; cvta.to.shared.u64 t, %1; cvt.u32.u64 %0, t; }" : "=r"(a) : "l"(p));
    return a;
}
__device__ __forceinline__ void ldsm_x4(uint32_t* r, uint32_t addr) {
    asm volatile("ldmatrix.sync.aligned.m8n8.x4.shared.b16 {%0,%1,%2,%3}, [%4];"
                 : "=r"(r[0]), "=r"(r[1]), "=r"(r[2]), "=r"(r[3]) : "r"(addr));
}
__device__ __forceinline__ void mma_f16(float* d, const uint32_t* a, uint32_t b0, uint32_t b1) {
    asm volatile(
        "mma.sync.aligned.m16n8k16.row.col.f32.f16.f16.f32 "
        "{%0,%1,%2,%3}, {%4,%5,%6,%7}, {%8,%9}, {%0,%1,%2,%3};"
        : "+f"(d[0]), "+f"(d[1]), "+f"(d[2]), "+f"(d[3])
        : "r"(a[0]), "r"(a[1]), "r"(a[2]), "r"(a[3]), "r"(b0), "r"(b1));
}
__device__ __forceinline__ void cp_async16(uint32_t dst, const void* src) {
    asm volatile("cp.async.cg.shared.global [%0], [%1], 16;" :: "r"(dst), "l"(src));
}
#define CP_COMMIT() asm volatile("cp.async.commit_group;" ::: "memory")
#define CP_WAIT0()  asm volatile("cp.async.wait_group 0;" ::: "memory")

// ---------------- Kernel 1: Wh = h @ W (fp16 3-term), s1, s2, WhT fp16 ----------------
// 128 CTAs x 512 thr (16 warps); 64 rows each.
#define R1    528                     // 256 fp16 + 16B pad
#define AH1   0
#define AL1   (64 * R1)               // 33792
#define BH1   (2 * 64 * R1)           // 67584
#define BL1   (BH1 + 128 * R1)        // 135168
#define K1_SMEM_BYTES (BL1 + 128 * R1)  // 202752
#define ASTG_OFF  0                   // fp32 stage [64][132] (reuses A region post-MMA)
#define AVEC_OFF  (64 * 132 * 4)

__global__ __launch_bounds__(512, 1) void k1_gemm_s(
    const float* __restrict__ h, const float* __restrict__ W,
    const float* __restrict__ a)
{
    extern __shared__ char base[];
    const uint32_t sb = smem_u32(base);
    const int t    = threadIdx.x;
    const int lane = t & 31;
    const int w    = t >> 5;            // 0..15
    const int row0 = blockIdx.x * 64;

    // ---- stage h tile (64x256) -> fp16 hi/lo ----
#pragma unroll
    for (int p = 0; p < 8; p++) {
        int id = t + p * 512;             // 0..4095 float4s
        int r = id >> 6, c4 = id & 63;
        float4 v = *(const float4*)&h[(size_t)(row0 + r) * FIN + c4 * 4];
        __half hi0 = __float2half_rn(v.x), hi1 = __float2half_rn(v.y);
        __half hi2 = __float2half_rn(v.z), hi3 = __float2half_rn(v.w);
        __half2 hp0, hp1, lp0, lp1;
        hp0.x = hi0; hp0.y = hi1; hp1.x = hi2; hp1.y = hi3;
        lp0.x = __float2half_rn(v.x - __half2float(hi0));
        lp0.y = __float2half_rn(v.y - __half2float(hi1));
        lp1.x = __float2half_rn(v.z - __half2float(hi2));
        lp1.y = __float2half_rn(v.w - __half2float(hi3));
        uint2 hv, lv;
        hv.x = *(uint32_t*)&hp0; hv.y = *(uint32_t*)&hp1;
        lv.x = *(uint32_t*)&lp0; lv.y = *(uint32_t*)&lp1;
        uint32_t off = (uint32_t)r * R1 + c4 * 8;
        *(uint2*)(base + AH1 + off) = hv;
        *(uint2*)(base + AL1 + off) = lv;
    }
    // ---- stage W transposed (WT[f][k]) fp16 hi/lo ----
#pragma unroll
    for (int p = 0; p < 16; p++) {
        int id = t + p * 512;             // 0..8191 float4s
        int r = id >> 5, c4 = id & 31;    // r = k, c4*4 = f
        float4 v = *(const float4*)&W[(size_t)r * FOUT + c4 * 4];
        float vv[4] = {v.x, v.y, v.z, v.w};
#pragma unroll
        for (int e = 0; e < 4; e++) {
            int f = c4 * 4 + e;
            __half hi = __float2half_rn(vv[e]);
            __half lo = __float2half_rn(vv[e] - __half2float(hi));
            *(__half*)(base + BH1 + (uint32_t)f * R1 + r * 2) = hi;
            *(__half*)(base + BL1 + (uint32_t)f * R1 + r * 2) = lo;
        }
    }
    __syncthreads();

    // ---- MMA: 16 warps, warp tile m16 x n32, 3-term split over K=256 ----
    const int mrow0 = (w & 3) * 16;
    const int ncol0 = (w >> 2) * 32;
    float acc[16];
#pragma unroll
    for (int q = 0; q < 16; q++) acc[q] = 0.0f;

    const uint32_t aH = sb + AH1 + (uint32_t)(mrow0 + (lane & 15)) * R1 + (lane >> 4) * 16;
    const uint32_t aL = aH + (AL1 - AH1);
    const uint32_t bH = sb + BH1 + (uint32_t)(ncol0 + (lane & 15)) * R1 + (lane >> 4) * 16;
    const uint32_t bL = bH + (BL1 - BH1);

#pragma unroll
    for (int ks = 0; ks < 16; ks++) {
        uint32_t Ah[4], Al[4], Bh[2][4], Bl[2][4];
        ldsm_x4(Ah, aH + ks * 32);
        ldsm_x4(Al, aL + ks * 32);
#pragma unroll
        for (int nb = 0; nb < 2; nb++) {
            ldsm_x4(Bh[nb], bH + nb * (16 * R1) + ks * 32);
            ldsm_x4(Bl[nb], bL + nb * (16 * R1) + ks * 32);
        }
#pragma unroll
        for (int nb = 0; nb < 2; nb++)
#pragma unroll
            for (int s = 0; s < 2; s++) {
                float* d = &acc[(nb * 2 + s) * 4];
                mma_f16(d, Ah, Bh[nb][s], Bh[nb][s + 2]);
                mma_f16(d, Ah, Bl[nb][s], Bl[nb][s + 2]);
                mma_f16(d, Al, Bh[nb][s], Bh[nb][s + 2]);
            }
    }
    __syncthreads();

    // ---- stage Wh fp32, then s1/s2 + transposed fp16 writeout ----
    float* stage = (float*)(base + ASTG_OFF);
    float* a_s   = (float*)(base + AVEC_OFF);
#pragma unroll
    for (int nb8 = 0; nb8 < 4; nb8++) {
        const float* d = &acc[nb8 * 4];
        int row = mrow0 + (lane >> 2);
        int col = ncol0 + nb8 * 8 + (lane & 3) * 2;
        stage[row * 132 + col]     = d[0];
        stage[row * 132 + col + 1] = d[1];
        stage[(row + 8) * 132 + col]     = d[2];
        stage[(row + 8) * 132 + col + 1] = d[3];
    }
    if (t < 256) a_s[t] = a[t];
    __syncthreads();

    if (t < 64) {
        float p1 = 0.f, p2 = 0.f;
#pragma unroll 8
        for (int c = 0; c < 128; c++) {
            float v = stage[t * 132 + c];
            p1 = fmaf(v, a_s[c], p1);
            p2 = fmaf(v, a_s[128 + c], p2);
        }
        g_s1[row0 + t] = p1;
        g_s2[row0 + t] = p2;
    }
    {
        int c  = t >> 2;                  // feature 0..127
        int rh = (t & 3) * 16;            // 16-row strip
#pragma unroll
        for (int r = 0; r < 16; r += 2) {
            float v0 = stage[(rh + r) * 132 + c];
            float v1 = stage[(rh + r + 1) * 132 + c];
            __half2 hp; hp.x = __float2half_rn(v0); hp.y = __float2half_rn(v1);
            *(__half2*)&g_WhT[(size_t)c * NN + row0 + rh + r] = hp;
        }
    }
}

// ---------------- Kernel 2: pipelined fp16 warp-MMA attention ----------------
// 256 CTAs (64 i-tiles x 4 j-quarters), 2 CTAs/SM. i-tile 128 rows; 32 j-tiles of 64.
// A = P fp16 single, B = WhT fp16 single -> 1 mma per k16.
#define ROWB  144
#define TILEA (128 * ROWB)            // 18432
#define BOFF  TILEA
#define BUFB  (2 * TILEA)             // 36864
#define S1_OFF (2 * BUFB)             // 73728
#define K2_SMEM_BYTES (S1_OFF + 512)

__global__ __launch_bounds__(256, 2) void k2_attn(const int* __restrict__ adj)
{
    extern __shared__ char base[];
    const uint32_t sb = smem_u32(base);
    float* s1_s = (float*)(base + S1_OFF);

    const int t    = threadIdx.x;
    const int lane = t & 31;
    const int w    = t >> 5;
    const int tile = blockIdx.x >> 2;
    const int q    = blockIdx.x & 3;
    const int i0   = tile * 128;
    const int jbeg = q * 2048;

    const int mrow0 = (w & 1) * 64;   // 2 m-splits
    const int ncol0 = (w >> 1) * 32;  // 4 n-splits

    const int xrow = w * 16 + (lane >> 4);
    const int xcol = (lane & 15) * 4;
    const int bfr  = t >> 3;          // B staging: feature row base
    const int bch  = t & 7;           // 16B chunk in row

    if (t < 128) s1_s[t] = g_s1[i0 + t];
    __syncthreads();

    float acc[64];
#pragma unroll
    for (int z = 0; z < 64; z++) acc[z] = 0.0f;
    float den_p[8];
#pragma unroll
    for (int r = 0; r < 8; r++) den_p[r] = 0.0f;

    const uint32_t aLane = (uint32_t)(mrow0 + (lane & 15)) * ROWB + (lane >> 4) * 16;
    const uint32_t bLane = (uint32_t)(ncol0 + (lane & 15)) * ROWB + (lane >> 4) * 16;

    // ---------------- prologue: tile 0 ----------------
    {
        const int j0n = jbeg;
#pragma unroll
        for (int p = 0; p < 4; p++) {
            int f = bfr + p * 32;
            cp_async16(sb + BOFF + (uint32_t)f * ROWB + bch * 16,
                       &g_WhT[(size_t)f * NN + j0n + bch * 8]);
        }
        CP_COMMIT();
        float4 s2v = *(const float4*)&g_s2[j0n + xcol];
#pragma unroll
        for (int r = 0; r < 8; r++) {
            int rl = xrow + r * 2;
            int4 av = *(const int4*)&adj[(size_t)(i0 + rl) * NN + j0n + xcol];
            float s1v = s1_s[rl];
            float e0 = s1v + s2v.x, e1 = s1v + s2v.y, e2 = s1v + s2v.z, e3 = s1v + s2v.w;
            e0 = fmaxf(e0, 0.2f * e0); e1 = fmaxf(e1, 0.2f * e1);
            e2 = fmaxf(e2, 0.2f * e2); e3 = fmaxf(e3, 0.2f * e3);
            float p0 = (av.x > 0) ? __expf(e0) : 0.0f;
            float p1 = (av.y > 0) ? __expf(e1) : 0.0f;
            float p2 = (av.z > 0) ? __expf(e2) : 0.0f;
            float p3 = (av.w > 0) ? __expf(e3) : 0.0f;
            __half2 q01 = __floats2half2_rn(p0, p1);
            __half2 q23 = __floats2half2_rn(p2, p3);
            uint2 hv; hv.x = *(uint32_t*)&q01; hv.y = *(uint32_t*)&q23;
            *(uint2*)(base + (uint32_t)rl * ROWB + (lane & 15) * 8) = hv;
            den_p[r] += (p0 + p1) + (p2 + p3);
        }
        CP_WAIT0();
    }
    __syncthreads();

    // ---------------- main loop: 32 j-tiles of 64 ----------------
    for (int it = 0; it < 32; it++) {
        const uint32_t bufo = (uint32_t)(it & 1) * BUFB;
        const uint32_t nbuf = (uint32_t)((it + 1) & 1) * BUFB;
        const int has_next = (it < 31);
        const int j0n = jbeg + (it + 1) * 64;

        if (has_next) {
#pragma unroll
            for (int p = 0; p < 4; p++) {
                int f = bfr + p * 32;
                cp_async16(sb + nbuf + BOFF + (uint32_t)f * ROWB + bch * 16,
                           &g_WhT[(size_t)f * NN + j0n + bch * 8]);
            }
            CP_COMMIT();
        }

        // ---- MMA on current buffers (64 mma/warp) ----
        {
            const uint32_t aA = sb + bufo + aLane;
            const uint32_t aB = sb + bufo + BOFF + bLane;
#pragma unroll
            for (int ks = 0; ks < 4; ks++) {
                uint32_t Ah[4][4];
#pragma unroll
                for (int mb = 0; mb < 4; mb++)
                    ldsm_x4(Ah[mb], aA + mb * (16 * ROWB) + ks * 32);
                uint32_t Bh[2][4];
#pragma unroll
                for (int nb = 0; nb < 2; nb++)
                    ldsm_x4(Bh[nb], aB + nb * (16 * ROWB) + ks * 32);
#pragma unroll
                for (int mb = 0; mb < 4; mb++)
#pragma unroll
                    for (int nb = 0; nb < 2; nb++)
#pragma unroll
                        for (int s = 0; s < 2; s++)
                            mma_f16(&acc[(mb * 4 + nb * 2 + s) * 4],
                                    Ah[mb], Bh[nb][s], Bh[nb][s + 2]);
            }
        }

        // ---- exp/convert next tile -> A[nbuf] ----
        if (has_next) {
            float4 s2v = *(const float4*)&g_s2[j0n + xcol];
#pragma unroll
            for (int r = 0; r < 8; r++) {
                int rl = xrow + r * 2;
                int4 av = *(const int4*)&adj[(size_t)(i0 + rl) * NN + j0n + xcol];
                float s1v = s1_s[rl];
                float e0 = s1v + s2v.x, e1 = s1v + s2v.y, e2 = s1v + s2v.z, e3 = s1v + s2v.w;
                e0 = fmaxf(e0, 0.2f * e0); e1 = fmaxf(e1, 0.2f * e1);
                e2 = fmaxf(e2, 0.2f * e2); e3 = fmaxf(e3, 0.2f * e3);
                float p0 = (av.x > 0) ? __expf(e0) : 0.0f;
                float p1 = (av.y > 0) ? __expf(e1) : 0.0f;
                float p2 = (av.z > 0) ? __expf(e2) : 0.0f;
                float p3 = (av.w > 0) ? __expf(e3) : 0.0f;
                __half2 q01 = __floats2half2_rn(p0, p1);
                __half2 q23 = __floats2half2_rn(p2, p3);
                uint2 hv; hv.x = *(uint32_t*)&q01; hv.y = *(uint32_t*)&q23;
                *(uint2*)(base + nbuf + (uint32_t)rl * ROWB + (lane & 15) * 8) = hv;
                den_p[r] += (p0 + p1) + (p2 + p3);
            }
        }
        CP_WAIT0();
        __syncthreads();
    }

    // ---- den reduction (within 16-lane half groups) ----
#pragma unroll
    for (int r = 0; r < 8; r++) {
#pragma unroll
        for (int o = 8; o >= 1; o >>= 1)
            den_p[r] += __shfl_xor_sync(0xffffffffu, den_p[r], o);
    }
    if ((lane & 15) == 0) {
#pragma unroll
        for (int r = 0; r < 8; r++)
            g_den[(size_t)q * NN + i0 + xrow + r * 2] = den_p[r];
    }

    // ---- write numerator partial ----
#pragma unroll
    for (int mb = 0; mb < 4; mb++)
#pragma unroll
        for (int nb8 = 0; nb8 < 4; nb8++) {
            const float* d = &acc[(mb * 4 + nb8) * 4];
            int row = i0 + mrow0 + mb * 16 + (lane >> 2);
            int col = ncol0 + nb8 * 8 + (lane & 3) * 2;
            size_t o0 = ((size_t)q * NN + row) * FOUT + col;
            *(float2*)&g_num[o0] = make_float2(d[0], d[1]);
            *(float2*)&g_num[o0 + 8 * FOUT] = make_float2(d[2], d[3]);
        }
}

// ---------------- Kernel 3: combine 4 split-j partials ----------------
__global__ __launch_bounds__(256) void k3_combine(float* __restrict__ out)
{
    int idx = blockIdx.x * 256 + threadIdx.x;       // float4 index
    int i = idx >> 5;                                // row
    float inv = 1.0f / (((g_den[i] + g_den[NN + i]) +
                         (g_den[2 * NN + i] + g_den[3 * NN + i])));
    const size_t STR = (size_t)NN * FOUT;
    float4 a0 = *(const float4*)&g_num[(size_t)idx * 4];
    float4 a1 = *(const float4*)&g_num[STR + (size_t)idx * 4];
    float4 a2 = *(const float4*)&g_num[2 * STR + (size_t)idx * 4];
    float4 a3 = *(const float4*)&g_num[3 * STR + (size_t)idx * 4];
    float4 o;
    o.x = ((a0.x + a1.x) + (a2.x + a3.x)) * inv;
    o.y = ((a0.y + a1.y) + (a2.y + a3.y)) * inv;
    o.z = ((a0.z + a1.z) + (a2.z + a3.z)) * inv;
    o.w = ((a0.w + a1.w) + (a2.w + a3.w)) * inv;
    *(float4*)&out[(size_t)idx * 4] = o;
}

// ---------------- launcher ----------------
extern "C" void kernel_launch(void* const* d_in, const int* in_sizes, int n_in,
                              void* d_out, int out_size)
{
    const float* h   = (const float*)d_in[0];
    const int*   adj = (const int*)  d_in[1];
    const float* W   = (const float*)d_in[2];
    const float* a   = (const float*)d_in[3];
    float* out = (float*)d_out;
    (void)in_sizes; (void)n_in; (void)out_size;

    cudaFuncSetAttribute(k1_gemm_s, cudaFuncAttributeMaxDynamicSharedMemorySize, K1_SMEM_BYTES);
    cudaFuncSetAttribute(k2_attn,  cudaFuncAttributeMaxDynamicSharedMemorySize, K2_SMEM_BYTES);

    k1_gemm_s<<<NN / 64, 512, K1_SMEM_BYTES>>>(h, W, a);
    k2_attn<<<NN / 32, 256, K2_SMEM_BYTES>>>(adj);
    k3_combine<<<NN * FOUT / 4 / 256, 256>>>(out);
}

// round 7
// speedup vs baseline: 1.1576x; 1.1576x over previous
#include <cuda_runtime.h>
#include <cuda_fp16.h>
#include <cstdint>

#define NN   8192
#define FIN  256
#define FOUT 128

// ---------------- device scratch ----------------
__device__ __align__(16) __half g_Wh[NN * FOUT];       // [j][f] fp16, natural order
__device__ __align__(16) float  g_num[2 * NN * FOUT];  // split-j partials
__device__ float  g_den[2 * NN];
__device__ __align__(16) float4 g_e1[NN];              // (e^s1, e^{0.2 s1}, e^{-s1}, 0)
__device__ __align__(16) float2 g_e2[NN];              // (e^s2, e^{0.2 s2})

// ---------------- helpers ----------------
__device__ __forceinline__ uint32_t smem_u32(const void* p) {
    uint32_t a;
    asm("{ .reg .u64 t; cvta.to.shared.u64 t, %1; cvt.u32.u64 %0, t; }" : "=r"(a) : "l"(p));
    return a;
}
__device__ __forceinline__ void ldsm_x4(uint32_t* r, uint32_t addr) {
    asm volatile("ldmatrix.sync.aligned.m8n8.x4.shared.b16 {%0,%1,%2,%3}, [%4];"
                 : "=r"(r[0]), "=r"(r[1]), "=r"(r[2]), "=r"(r[3]) : "r"(addr));
}
__device__ __forceinline__ void ldsm_x4_t(uint32_t* r, uint32_t addr) {
    asm volatile("ldmatrix.sync.aligned.m8n8.x4.trans.shared.b16 {%0,%1,%2,%3}, [%4];"
                 : "=r"(r[0]), "=r"(r[1]), "=r"(r[2]), "=r"(r[3]) : "r"(addr));
}
__device__ __forceinline__ void mma_f16(float* d, const uint32_t* a, uint32_t b0, uint32_t b1) {
    asm volatile(
        "mma.sync.aligned.m16n8k16.row.col.f32.f16.f16.f32 "
        "{%0,%1,%2,%3}, {%4,%5,%6,%7}, {%8,%9}, {%0,%1,%2,%3};"
        : "+f"(d[0]), "+f"(d[1]), "+f"(d[2]), "+f"(d[3])
        : "r"(a[0]), "r"(a[1]), "r"(a[2]), "r"(a[3]), "r"(b0), "r"(b1));
}
__device__ __forceinline__ void cp_async16(uint32_t dst, const void* src) {
    asm volatile("cp.async.cg.shared.global [%0], [%1], 16;" :: "r"(dst), "l"(src));
}
#define CP_COMMIT() asm volatile("cp.async.commit_group;" ::: "memory")
#define CP_WAIT0()  asm volatile("cp.async.wait_group 0;" ::: "memory")
__device__ __forceinline__ uint32_t h2u(__half2 h) { return *(uint32_t*)&h; }

// ---------------- Kernel 1 ----------------
// 128 CTAs x 512 thr; 64 rows. Wh=h@W via fp16 3-term mma; outputs g_Wh [j][f],
// g_e1/g_e2 score tables.
#define R1H 528
#define R1W 272
#define HH_OFF 0
#define HL_OFF (64 * R1H)                 // 33792
#define WH_OFF (2 * 64 * R1H)             // 67584
#define WL_OFF (WH_OFF + 256 * R1W)       // 137216
#define K1_SMEM (WL_OFF + 256 * R1W)      // 206848
#define AVEC_OFF (64 * 132 * 4)           // a[] copy, inside stage overlay region

__global__ __launch_bounds__(512, 1) void k1_gemm_s(
    const float* __restrict__ h, const float* __restrict__ W,
    const float* __restrict__ a)
{
    extern __shared__ char base[];
    const uint32_t sb = smem_u32(base);
    const int t = threadIdx.x, lane = t & 31, w = t >> 5;
    const int row0 = blockIdx.x * 64;

    // stage h (64x256) fp16 hi/lo, [row][k]
#pragma unroll
    for (int p = 0; p < 8; p++) {
        int id = t + p * 512;
        int r = id >> 6, c4 = id & 63;
        float4 v = *(const float4*)&h[(size_t)(row0 + r) * FIN + c4 * 4];
        __half x0 = __float2half_rn(v.x), x1 = __float2half_rn(v.y);
        __half x2 = __float2half_rn(v.z), x3 = __float2half_rn(v.w);
        __half2 hp0, hp1, lp0, lp1;
        hp0.x = x0; hp0.y = x1; hp1.x = x2; hp1.y = x3;
        lp0.x = __float2half_rn(v.x - __half2float(x0));
        lp0.y = __float2half_rn(v.y - __half2float(x1));
        lp1.x = __float2half_rn(v.z - __half2float(x2));
        lp1.y = __float2half_rn(v.w - __half2float(x3));
        uint32_t off = (uint32_t)r * R1H + c4 * 8;
        *(uint2*)(base + HH_OFF + off) = make_uint2(h2u(hp0), h2u(hp1));
        *(uint2*)(base + HL_OFF + off) = make_uint2(h2u(lp0), h2u(lp1));
    }
    // stage W (256x128) fp16 hi/lo, [k][f] (conflict-free)
#pragma unroll
    for (int p = 0; p < 16; p++) {
        int id = t + p * 512;
        int k = id >> 5, f4 = id & 31;
        float4 v = *(const float4*)&W[(size_t)k * FOUT + f4 * 4];
        __half x0 = __float2half_rn(v.x), x1 = __float2half_rn(v.y);
        __half x2 = __float2half_rn(v.z), x3 = __float2half_rn(v.w);
        __half2 hp0, hp1, lp0, lp1;
        hp0.x = x0; hp0.y = x1; hp1.x = x2; hp1.y = x3;
        lp0.x = __float2half_rn(v.x - __half2float(x0));
        lp0.y = __float2half_rn(v.y - __half2float(x1));
        lp1.x = __float2half_rn(v.z - __half2float(x2));
        lp1.y = __float2half_rn(v.w - __half2float(x3));
        uint32_t off = (uint32_t)k * R1W + f4 * 8;
        *(uint2*)(base + WH_OFF + off) = make_uint2(h2u(hp0), h2u(hp1));
        *(uint2*)(base + WL_OFF + off) = make_uint2(h2u(lp0), h2u(lp1));
    }
    __syncthreads();

    // 16 warps: warp = m16 x n32
    const int mrow0 = (w & 3) * 16;
    const int ncol0 = (w >> 2) * 32;
    float acc[16];
#pragma unroll
    for (int q = 0; q < 16; q++) acc[q] = 0.0f;

    const uint32_t aH = sb + HH_OFF + (uint32_t)(mrow0 + (lane & 15)) * R1H + (lane >> 4) * 16;
    const uint32_t aL = aH + (HL_OFF - HH_OFF);

#pragma unroll
    for (int ks = 0; ks < 16; ks++) {
        uint32_t Ah[4], Al[4];
        ldsm_x4(Ah, aH + ks * 32);
        ldsm_x4(Al, aL + ks * 32);
#pragma unroll
        for (int ng = 0; ng < 2; ng++) {
            uint32_t bo = (uint32_t)(ks * 16 + (lane & 15)) * R1W +
                          (ncol0 + ng * 16 + (lane >> 4) * 8) * 2;
            uint32_t Bh[4], Bl[4];
            ldsm_x4_t(Bh, sb + WH_OFF + bo);
            ldsm_x4_t(Bl, sb + WL_OFF + bo);
#pragma unroll
            for (int s = 0; s < 2; s++) {
                float* d = &acc[(ng * 2 + s) * 4];
                mma_f16(d, Ah, Bh[s * 2], Bh[s * 2 + 1]);
                mma_f16(d, Ah, Bl[s * 2], Bl[s * 2 + 1]);
                mma_f16(d, Al, Bh[s * 2], Bh[s * 2 + 1]);
            }
        }
    }
    __syncthreads();

    // stage fp32 [64][132]
    float* stage = (float*)base;
    float* a_s   = (float*)(base + AVEC_OFF);
#pragma unroll
    for (int nb = 0; nb < 4; nb++) {
        const float* d = &acc[nb * 4];
        int row = mrow0 + (lane >> 2);
        int col = ncol0 + (nb >> 1) * 16 + (nb & 1) * 8 + (lane & 3) * 2;
        stage[row * 132 + col]     = d[0];
        stage[row * 132 + col + 1] = d[1];
        stage[(row + 8) * 132 + col]     = d[2];
        stage[(row + 8) * 132 + col + 1] = d[3];
    }
    if (t < 256) a_s[t] = a[t];
    __syncthreads();

    if (t < 64) {
        float p1 = 0.f, p2 = 0.f;
#pragma unroll 8
        for (int c = 0; c < 128; c++) {
            float v = stage[t * 132 + c];
            p1 = fmaf(v, a_s[c], p1);
            p2 = fmaf(v, a_s[128 + c], p2);
        }
        g_e1[row0 + t] = make_float4(__expf(p1), __expf(0.2f * p1), __expf(-p1), 0.0f);
        g_e2[row0 + t] = make_float2(__expf(p2), __expf(0.2f * p2));
    }
    // Wh writeout [j][f] fp16 (natural order)
    {
        int row = t >> 3;
        int f0  = (t & 7) * 16;
#pragma unroll
        for (int q = 0; q < 8; q++) {
            __half2 hp;
            hp.x = __float2half_rn(stage[row * 132 + f0 + q * 2]);
            hp.y = __float2half_rn(stage[row * 132 + f0 + q * 2 + 1]);
            *(__half2*)&g_Wh[(size_t)(row0 + row) * FOUT + f0 + q * 2] = hp;
        }
    }
}

// ---------------- Kernel 2 ----------------
// 128 CTAs (64 i-tiles x 2 j-halves) x 512 thr, 1 CTA/SM.
// i-tile 128 rows; 32 j-tiles of 128. Warp = m16 x n64.
// A (P-values) generated straight into mma fragments (registers). B via
// cp.async + ldmatrix.trans. e2 LUT in smem. One __syncthreads per tile.
#define RB     272
#define BTILE  (128 * RB)          // 34816
#define LUT_OFF (2 * BTILE)        // 69632
#define K2_SMEM (LUT_OFF + 2048 + 256)

__global__ __launch_bounds__(512, 1) void k2_attn(const int* __restrict__ adj)
{
    extern __shared__ char base[];
    const uint32_t sb = smem_u32(base);

    const int t = threadIdx.x, lane = t & 31, w = t >> 5;
    const int tile = blockIdx.x >> 1;
    const int jh   = blockIdx.x & 1;
    const int i0   = tile * 128;
    const int jbeg = jh * 4096;

    const int mrow0 = (w & 7) * 16;
    const int F0    = (w >> 3) * 64;
    const int cq    = (lane & 3) * 2;

    const int gr0 = i0 + mrow0 + (lane >> 2);
    const int gr1 = gr0 + 8;
    const float4 e1a = g_e1[gr0];
    const float4 e1b = g_e1[gr1];

    float acc[32];
#pragma unroll
    for (int q = 0; q < 32; q++) acc[q] = 0.0f;
    float den0 = 0.0f, den1 = 0.0f;

    // B staging geometry: 2048 chunks of 16B, 4 per thread
    const int bj = t >> 4;            // first j-row (of 4, stride 32)
    const int bc = t & 15;            // 16B chunk within row

    // ---- prologue: stage tile 0 (B + LUT), prime adj ring (ksg 0,1) ----
    {
#pragma unroll
        for (int p = 0; p < 4; p++) {
            int j = bj + p * 32;
            cp_async16(sb + (uint32_t)j * RB + bc * 16,
                       &g_Wh[(size_t)(jbeg + j) * FOUT + bc * 8]);
        }
        if (t < 64)
            cp_async16(sb + LUT_OFF + t * 16, (const char*)g_e2 + (size_t)jbeg * 8 + t * 16);
        CP_COMMIT();
    }
    int2 aq[2][4];
#pragma unroll
    for (int s = 0; s < 2; s++) {
        int jc = jbeg + s * 16 + cq;
        aq[s][0] = *(const int2*)&adj[(size_t)gr0 * NN + jc];
        aq[s][1] = *(const int2*)&adj[(size_t)gr1 * NN + jc];
        aq[s][2] = *(const int2*)&adj[(size_t)gr0 * NN + jc + 8];
        aq[s][3] = *(const int2*)&adj[(size_t)gr1 * NN + jc + 8];
    }
    CP_WAIT0();
    __syncthreads();

    // ---- main loop: 32 tiles of 128 j ----
    for (int it = 0; it < 32; it++) {
        const uint32_t bbuf = sb + (uint32_t)(it & 1) * BTILE;
        const uint32_t lutb = sb + LUT_OFF + (uint32_t)(it & 1) * 1024;

        if (it < 31) {
            const int j0n = jbeg + (it + 1) * 128;
            const uint32_t nb = sb + (uint32_t)((it + 1) & 1) * BTILE;
#pragma unroll
            for (int p = 0; p < 4; p++) {
                int j = bj + p * 32;
                cp_async16(nb + (uint32_t)j * RB + bc * 16,
                           &g_Wh[(size_t)(j0n + j) * FOUT + bc * 8]);
            }
            if (t < 64)
                cp_async16(sb + LUT_OFF + (uint32_t)((it + 1) & 1) * 1024 + t * 16,
                           (const char*)g_e2 + (size_t)j0n * 8 + t * 16);
            CP_COMMIT();
        }

#pragma unroll
        for (int ks = 0; ks < 8; ks++) {
            // LUT: (e2p,e2n) pairs for cols cq,cq+1 and cq+8,cq+9
            float4 lA = *(const float4*)(base + (lutb - sb) + ks * 128 + cq * 8);
            float4 lB = *(const float4*)(base + (lutb - sb) + ks * 128 + cq * 8 + 64);
            int2 A0 = aq[ks & 1][0], A1 = aq[ks & 1][1];
            int2 B0 = aq[ks & 1][2], B1 = aq[ks & 1][3];

            // p = mask * (e2p>=e1r ? e1p*e2p : e1n*e2n)
            float p00 = (A0.x > 0) ? ((lA.x >= e1a.z) ? e1a.x * lA.x : e1a.y * lA.y) : 0.0f;
            float p01 = (A0.y > 0) ? ((lA.z >= e1a.z) ? e1a.x * lA.z : e1a.y * lA.w) : 0.0f;
            float p10 = (A1.x > 0) ? ((lA.x >= e1b.z) ? e1b.x * lA.x : e1b.y * lA.y) : 0.0f;
            float p11 = (A1.y > 0) ? ((lA.z >= e1b.z) ? e1b.x * lA.z : e1b.y * lA.w) : 0.0f;
            float q00 = (B0.x > 0) ? ((lB.x >= e1a.z) ? e1a.x * lB.x : e1a.y * lB.y) : 0.0f;
            float q01 = (B0.y > 0) ? ((lB.z >= e1a.z) ? e1a.x * lB.z : e1a.y * lB.w) : 0.0f;
            float q10 = (B1.x > 0) ? ((lB.x >= e1b.z) ? e1b.x * lB.x : e1b.y * lB.y) : 0.0f;
            float q11 = (B1.y > 0) ? ((lB.z >= e1b.z) ? e1b.x * lB.z : e1b.y * lB.w) : 0.0f;

            den0 += (p00 + p01) + (q00 + q01);
            den1 += (p10 + p11) + (q10 + q11);

            uint32_t A[4];
            A[0] = h2u(__floats2half2_rn(p00, p01));
            A[1] = h2u(__floats2half2_rn(p10, p11));
            A[2] = h2u(__floats2half2_rn(q00, q01));
            A[3] = h2u(__floats2half2_rn(q10, q11));

            // refill ring for ksg+2 (crosses into next tile at ks>=6)
            {
                int ksg2 = it * 8 + ks + 2;
                if (ksg2 > 255) ksg2 = 255;
                int jc = jbeg + (ksg2 >> 3) * 128 + (ksg2 & 7) * 16 + cq;
                aq[ks & 1][0] = *(const int2*)&adj[(size_t)gr0 * NN + jc];
                aq[ks & 1][1] = *(const int2*)&adj[(size_t)gr1 * NN + jc];
                aq[ks & 1][2] = *(const int2*)&adj[(size_t)gr0 * NN + jc + 8];
                aq[ks & 1][3] = *(const int2*)&adj[(size_t)gr1 * NN + jc + 8];
            }

            // B frags (trans) + mma: n64 = 4 groups of n16
#pragma unroll
            for (int ng = 0; ng < 4; ng++) {
                uint32_t B[4];
                uint32_t bo = (uint32_t)(ks * 16 + (lane & 15)) * RB +
                              (F0 + ng * 16 + (lane >> 4) * 8) * 2;
                ldsm_x4_t(B, bbuf + bo);
                mma_f16(&acc[(ng * 2) * 4],     A, B[0], B[1]);
                mma_f16(&acc[(ng * 2 + 1) * 4], A, B[2], B[3]);
            }
        }
        CP_WAIT0();
        __syncthreads();
    }

    // ---- den: quad reduce, one writer ----
    den0 += __shfl_xor_sync(0xffffffffu, den0, 1);
    den0 += __shfl_xor_sync(0xffffffffu, den0, 2);
    den1 += __shfl_xor_sync(0xffffffffu, den1, 1);
    den1 += __shfl_xor_sync(0xffffffffu, den1, 2);
    if ((lane & 3) == 0) {
        g_den[(size_t)jh * NN + gr0] = den0;
        g_den[(size_t)jh * NN + gr1] = den1;
    }

    // ---- numerator writeout ----
#pragma unroll
    for (int nb = 0; nb < 8; nb++) {
        const float* d = &acc[nb * 4];
        int col = F0 + nb * 8 + cq;
        size_t o0 = ((size_t)jh * NN + gr0) * FOUT + col;
        size_t o1 = ((size_t)jh * NN + gr1) * FOUT + col;
        *(float2*)&g_num[o0] = make_float2(d[0], d[1]);
        *(float2*)&g_num[o1] = make_float2(d[2], d[3]);
    }
}

// ---------------- Kernel 3: combine ----------------
__global__ __launch_bounds__(256) void k3_combine(float* __restrict__ out)
{
    int idx = blockIdx.x * 256 + threadIdx.x;       // float4 index
    int i = idx >> 5;
    float inv = 1.0f / (g_den[i] + g_den[NN + i]);
    float4 a = *(const float4*)&g_num[(size_t)idx * 4];
    float4 b = *(const float4*)&g_num[(size_t)NN * FOUT + (size_t)idx * 4];
    float4 o;
    o.x = (a.x + b.x) * inv; o.y = (a.y + b.y) * inv;
    o.z = (a.z + b.z) * inv; o.w = (a.w + b.w) * inv;
    *(float4*)&out[(size_t)idx * 4] = o;
}

// ---------------- launcher ----------------
extern "C" void kernel_launch(void* const* d_in, const int* in_sizes, int n_in,
                              void* d_out, int out_size)
{
    const float* h   = (const float*)d_in[0];
    const int*   adj = (const int*)  d_in[1];
    const float* W   = (const float*)d_in[2];
    const float* a   = (const float*)d_in[3];
    float* out = (float*)d_out;
    (void)in_sizes; (void)n_in; (void)out_size;

    cudaFuncSetAttribute(k1_gemm_s, cudaFuncAttributeMaxDynamicSharedMemorySize, K1_SMEM);
    cudaFuncSetAttribute(k2_attn,  cudaFuncAttributeMaxDynamicSharedMemorySize, K2_SMEM);

    k1_gemm_s<<<NN / 64, 512, K1_SMEM>>>(h, W, a);
    k2_attn<<<NN / 64, 512, K2_SMEM>>>(adj);
    k3_combine<<<NN * FOUT / 4 / 256, 256>>>(out);
}

// round 8
// speedup vs baseline: 1.4383x; 1.2424x over previous
#include <cuda_runtime.h>
#include <cuda_fp16.h>
#include <cstdint>

#define NN   8192
#define FIN  256
#define FOUT 128

// ---------------- device scratch ----------------
__device__ __align__(16) __half g_Wh[NN * FOUT];       // [j][f] fp16
__device__ __align__(16) float  g_num[2 * NN * FOUT];  // split-j partials
__device__ float  g_den[2 * NN];
__device__ __align__(16) float4 g_e1[NN];              // (e^s1, e^{0.2 s1}, s1, 0)
__device__ __align__(16) uint4  g_lut[NN / 2];         // per j-pair: {e2p2, e2n2, s22, 0} fp16x2

// ---------------- helpers ----------------
__device__ __forceinline__ uint32_t smem_u32(const void* p) {
    uint32_t a;
    asm("{ .reg .u64 t; cvta.to.shared.u64 t, %1; cvt.u32.u64 %0, t; }" : "=r"(a) : "l"(p));
    return a;
}
__device__ __forceinline__ void ldsm_x4(uint32_t* r, uint32_t addr) {
    asm volatile("ldmatrix.sync.aligned.m8n8.x4.shared.b16 {%0,%1,%2,%3}, [%4];"
                 : "=r"(r[0]), "=r"(r[1]), "=r"(r[2]), "=r"(r[3]) : "r"(addr));
}
__device__ __forceinline__ void ldsm_x4_t(uint32_t* r, uint32_t addr) {
    asm volatile("ldmatrix.sync.aligned.m8n8.x4.trans.shared.b16 {%0,%1,%2,%3}, [%4];"
                 : "=r"(r[0]), "=r"(r[1]), "=r"(r[2]), "=r"(r[3]) : "r"(addr));
}
__device__ __forceinline__ void mma_f16(float* d, const uint32_t* a, uint32_t b0, uint32_t b1) {
    asm volatile(
        "mma.sync.aligned.m16n8k16.row.col.f32.f16.f16.f32 "
        "{%0,%1,%2,%3}, {%4,%5,%6,%7}, {%8,%9}, {%0,%1,%2,%3};"
        : "+f"(d[0]), "+f"(d[1]), "+f"(d[2]), "+f"(d[3])
        : "r"(a[0]), "r"(a[1]), "r"(a[2]), "r"(a[3]), "r"(b0), "r"(b1));
}
__device__ __forceinline__ void cp_async16(uint32_t dst, const void* src) {
    asm volatile("cp.async.cg.shared.global [%0], [%1], 16;" :: "r"(dst), "l"(src));
}
#define CP_COMMIT() asm volatile("cp.async.commit_group;" ::: "memory")
#define CP_WAIT0()  asm volatile("cp.async.wait_group 0;" ::: "memory")
__device__ __forceinline__ uint32_t h2u(__half2 h) { return *(uint32_t*)&h; }
__device__ __forceinline__ uint32_t bcast_h2(float f) {
    __half2 v = __float2half2_rn(f);
    return *(uint32_t*)&v;
}

// A-fragment half2 gen: p = adjmask & (s2>=-s1 ? e1p*e2p : e1n*e2n), all f16x2.
__device__ __forceinline__ uint32_t genA(uint32_t e2p2, uint32_t e2n2, uint32_t s22,
                                         uint32_t e1p, uint32_t e1n, uint32_t ns1,
                                         int2 adj) {
    uint32_t pp, pn, mk;
    asm("mul.f16x2 %0, %1, %2;" : "=r"(pp) : "r"(e1p), "r"(e2p2));
    asm("mul.f16x2 %0, %1, %2;" : "=r"(pn) : "r"(e1n), "r"(e2n2));
    asm("set.ge.u32.f16x2 %0, %1, %2;" : "=r"(mk) : "r"(s22), "r"(ns1));
    uint32_t sel = (pp & mk) | (pn & ~mk);
    uint32_t am  = (uint32_t)adj.x * 0xFFFFu + (uint32_t)adj.y * 0xFFFF0000u;
    return sel & am;
}

// ---------------- Kernel 1 ----------------
#define R1H 528
#define R1W 272
#define HH_OFF 0
#define HL_OFF (64 * R1H)
#define WH_OFF (2 * 64 * R1H)
#define WL_OFF (WH_OFF + 256 * R1W)
#define K1_SMEM (WL_OFF + 256 * R1W)
#define AVEC_OFF (64 * 132 * 4)

__global__ __launch_bounds__(512, 1) void k1_gemm_s(
    const float* __restrict__ h, const float* __restrict__ W,
    const float* __restrict__ a)
{
    extern __shared__ char base[];
    const uint32_t sb = smem_u32(base);
    const int t = threadIdx.x, lane = t & 31, w = t >> 5;
    const int row0 = blockIdx.x * 64;

#pragma unroll
    for (int p = 0; p < 8; p++) {
        int id = t + p * 512;
        int r = id >> 6, c4 = id & 63;
        float4 v = *(const float4*)&h[(size_t)(row0 + r) * FIN + c4 * 4];
        __half x0 = __float2half_rn(v.x), x1 = __float2half_rn(v.y);
        __half x2 = __float2half_rn(v.z), x3 = __float2half_rn(v.w);
        __half2 hp0, hp1, lp0, lp1;
        hp0.x = x0; hp0.y = x1; hp1.x = x2; hp1.y = x3;
        lp0.x = __float2half_rn(v.x - __half2float(x0));
        lp0.y = __float2half_rn(v.y - __half2float(x1));
        lp1.x = __float2half_rn(v.z - __half2float(x2));
        lp1.y = __float2half_rn(v.w - __half2float(x3));
        uint32_t off = (uint32_t)r * R1H + c4 * 8;
        *(uint2*)(base + HH_OFF + off) = make_uint2(h2u(hp0), h2u(hp1));
        *(uint2*)(base + HL_OFF + off) = make_uint2(h2u(lp0), h2u(lp1));
    }
#pragma unroll
    for (int p = 0; p < 16; p++) {
        int id = t + p * 512;
        int k = id >> 5, f4 = id & 31;
        float4 v = *(const float4*)&W[(size_t)k * FOUT + f4 * 4];
        __half x0 = __float2half_rn(v.x), x1 = __float2half_rn(v.y);
        __half x2 = __float2half_rn(v.z), x3 = __float2half_rn(v.w);
        __half2 hp0, hp1, lp0, lp1;
        hp0.x = x0; hp0.y = x1; hp1.x = x2; hp1.y = x3;
        lp0.x = __float2half_rn(v.x - __half2float(x0));
        lp0.y = __float2half_rn(v.y - __half2float(x1));
        lp1.x = __float2half_rn(v.z - __half2float(x2));
        lp1.y = __float2half_rn(v.w - __half2float(x3));
        uint32_t off = (uint32_t)k * R1W + f4 * 8;
        *(uint2*)(base + WH_OFF + off) = make_uint2(h2u(hp0), h2u(hp1));
        *(uint2*)(base + WL_OFF + off) = make_uint2(h2u(lp0), h2u(lp1));
    }
    __syncthreads();

    const int mrow0 = (w & 3) * 16;
    const int ncol0 = (w >> 2) * 32;
    float acc[16];
#pragma unroll
    for (int q = 0; q < 16; q++) acc[q] = 0.0f;

    const uint32_t aH = sb + HH_OFF + (uint32_t)(mrow0 + (lane & 15)) * R1H + (lane >> 4) * 16;
    const uint32_t aL = aH + (HL_OFF - HH_OFF);

#pragma unroll
    for (int ks = 0; ks < 16; ks++) {
        uint32_t Ah[4], Al[4];
        ldsm_x4(Ah, aH + ks * 32);
        ldsm_x4(Al, aL + ks * 32);
#pragma unroll
        for (int ng = 0; ng < 2; ng++) {
            uint32_t bo = (uint32_t)(ks * 16 + (lane & 15)) * R1W +
                          (ncol0 + ng * 16 + (lane >> 4) * 8) * 2;
            uint32_t Bh[4], Bl[4];
            ldsm_x4_t(Bh, sb + WH_OFF + bo);
            ldsm_x4_t(Bl, sb + WL_OFF + bo);
#pragma unroll
            for (int s = 0; s < 2; s++) {
                float* d = &acc[(ng * 2 + s) * 4];
                mma_f16(d, Ah, Bh[s * 2], Bh[s * 2 + 1]);
                mma_f16(d, Ah, Bl[s * 2], Bl[s * 2 + 1]);
                mma_f16(d, Al, Bh[s * 2], Bh[s * 2 + 1]);
            }
        }
    }
    __syncthreads();

    float* stage = (float*)base;
    float* a_s   = (float*)(base + AVEC_OFF);
#pragma unroll
    for (int nb = 0; nb < 4; nb++) {
        const float* d = &acc[nb * 4];
        int row = mrow0 + (lane >> 2);
        int col = ncol0 + (nb >> 1) * 16 + (nb & 1) * 8 + (lane & 3) * 2;
        stage[row * 132 + col]     = d[0];
        stage[row * 132 + col + 1] = d[1];
        stage[(row + 8) * 132 + col]     = d[2];
        stage[(row + 8) * 132 + col + 1] = d[3];
    }
    if (t < 256) a_s[t] = a[t];
    __syncthreads();

    if (t < 64) {
        float p1 = 0.f, p2 = 0.f;
#pragma unroll 8
        for (int c = 0; c < 128; c++) {
            float v = stage[t * 132 + c];
            p1 = fmaf(v, a_s[c], p1);
            p2 = fmaf(v, a_s[128 + c], p2);
        }
        g_e1[row0 + t] = make_float4(__expf(p1), __expf(0.2f * p1), p1, 0.0f);
        float e2p = __expf(p2), e2n = __expf(0.2f * p2);
        float e2p_n = __shfl_down_sync(0xffffffffu, e2p, 1);
        float e2n_n = __shfl_down_sync(0xffffffffu, e2n, 1);
        float s2_n  = __shfl_down_sync(0xffffffffu, p2, 1);
        if ((t & 1) == 0) {
            __half2 a0 = __floats2half2_rn(e2p, e2p_n);
            __half2 b0 = __floats2half2_rn(e2n, e2n_n);
            __half2 c0 = __floats2half2_rn(p2, s2_n);
            uint4 e;
            e.x = h2u(a0); e.y = h2u(b0); e.z = h2u(c0); e.w = 0;
            g_lut[(row0 + t) >> 1] = e;
        }
    }
    {
        int row = t >> 3;
        int f0  = (t & 7) * 16;
#pragma unroll
        for (int q = 0; q < 8; q++) {
            __half2 hp;
            hp.x = __float2half_rn(stage[row * 132 + f0 + q * 2]);
            hp.y = __float2half_rn(stage[row * 132 + f0 + q * 2 + 1]);
            *(__half2*)&g_Wh[(size_t)(row0 + row) * FOUT + f0 + q * 2] = hp;
        }
    }
}

// ---------------- Kernel 2 ----------------
// 128 CTAs (64 i-tiles x 2 j-halves) x 512 thr. i-tile 128 rows; 32 j-tiles of 128.
// A-frags generated in f16x2 registers (no cvt). den via ones-column mma.
#define RB     272                 // 128 Wh halfs (256B) + 8 pad halfs ({1,0..})
#define BTILE  (128 * RB)          // 34816
#define LUT_OFF (2 * BTILE)        // 69632
#define K2_SMEM (LUT_OFF + 2048 + 256)

__global__ __launch_bounds__(512, 1) void k2_attn(const int* __restrict__ adj)
{
    extern __shared__ char base[];
    const uint32_t sb = smem_u32(base);

    const int t = threadIdx.x, lane = t & 31, w = t >> 5;
    const int tile = blockIdx.x >> 1;
    const int jh   = blockIdx.x & 1;
    const int i0   = tile * 128;
    const int jbeg = jh * 4096;

    const int mrow0 = (w & 7) * 16;
    const int fg    = w >> 3;          // F-group: 0 or 1
    const int F0    = fg * 64;
    const int cq    = (lane & 3) * 2;

    const int gr0 = i0 + mrow0 + (lane >> 2);
    const int gr1 = gr0 + 8;
    const float4 E0 = g_e1[gr0];
    const float4 E1 = g_e1[gr1];
    const uint32_t e1p0 = bcast_h2(E0.x), e1n0 = bcast_h2(E0.y), ns10 = bcast_h2(-E0.z);
    const uint32_t e1p1 = bcast_h2(E1.x), e1n1 = bcast_h2(E1.y), ns11 = bcast_h2(-E1.z);

    float acc[32];
#pragma unroll
    for (int q = 0; q < 32; q++) acc[q] = 0.0f;
    float dden[4] = {0.f, 0.f, 0.f, 0.f};

    const int bj = t >> 4;
    const int bc = t & 15;

    // ---- init ones-pad in both buffers (cp.async never touches bytes 256..271) ----
    if (t < 128) {
        uint4 z = make_uint4(0x00003C00u, 0u, 0u, 0u);   // {1.0h, 0 x7}
        *(uint4*)(base + (uint32_t)t * RB + 256) = z;
        *(uint4*)(base + BTILE + (uint32_t)t * RB + 256) = z;
    }

    // ---- prologue: stage tile 0 (B + LUT), prime adj ring ----
    {
#pragma unroll
        for (int p = 0; p < 4; p++) {
            int j = bj + p * 32;
            cp_async16(sb + (uint32_t)j * RB + bc * 16,
                       &g_Wh[(size_t)(jbeg + j) * FOUT + bc * 8]);
        }
        if (t < 64)
            cp_async16(sb + LUT_OFF + t * 16, &g_lut[(jbeg >> 1) + t]);
        CP_COMMIT();
    }
    int2 aq[2][4];
#pragma unroll
    for (int s = 0; s < 2; s++) {
        int jc = jbeg + s * 16 + cq;
        aq[s][0] = *(const int2*)&adj[(size_t)gr0 * NN + jc];
        aq[s][1] = *(const int2*)&adj[(size_t)gr1 * NN + jc];
        aq[s][2] = *(const int2*)&adj[(size_t)gr0 * NN + jc + 8];
        aq[s][3] = *(const int2*)&adj[(size_t)gr1 * NN + jc + 8];
    }
    CP_WAIT0();
    __syncthreads();

    // hoisted ones-column B fragment (constant across all tiles)
    uint32_t Bones[4];
    ldsm_x4_t(Bones, sb + (uint32_t)(lane & 15) * RB + 256 + (uint32_t)(lane >> 4) * 16);

    // ---- main loop: 32 tiles of 128 j ----
    for (int it = 0; it < 32; it++) {
        const uint32_t bbuf = sb + (uint32_t)(it & 1) * BTILE;
        const uint32_t loff = LUT_OFF + (uint32_t)(it & 1) * 1024;

        if (it < 31) {
            const int j0n = jbeg + (it + 1) * 128;
            const uint32_t nb = sb + (uint32_t)((it + 1) & 1) * BTILE;
#pragma unroll
            for (int p = 0; p < 4; p++) {
                int j = bj + p * 32;
                cp_async16(nb + (uint32_t)j * RB + bc * 16,
                           &g_Wh[(size_t)(j0n + j) * FOUT + bc * 8]);
            }
            if (t < 64)
                cp_async16(sb + LUT_OFF + (uint32_t)((it + 1) & 1) * 1024 + t * 16,
                           &g_lut[(j0n >> 1) + t]);
            CP_COMMIT();
        }

#pragma unroll
        for (int ks = 0; ks < 8; ks++) {
            uint4 L0 = *(const uint4*)(base + loff + (ks * 8 + (lane & 3)) * 16);
            uint4 L1 = *(const uint4*)(base + loff + (ks * 8 + (lane & 3) + 4) * 16);

            uint32_t A[4];
            A[0] = genA(L0.x, L0.y, L0.z, e1p0, e1n0, ns10, aq[ks & 1][0]);
            A[1] = genA(L0.x, L0.y, L0.z, e1p1, e1n1, ns11, aq[ks & 1][1]);
            A[2] = genA(L1.x, L1.y, L1.z, e1p0, e1n0, ns10, aq[ks & 1][2]);
            A[3] = genA(L1.x, L1.y, L1.z, e1p1, e1n1, ns11, aq[ks & 1][3]);

            // refill adj ring for ksg+2
            {
                int ksg2 = it * 8 + ks + 2;
                if (ksg2 > 255) ksg2 = 255;
                int jc = jbeg + (ksg2 >> 3) * 128 + (ksg2 & 7) * 16 + cq;
                aq[ks & 1][0] = *(const int2*)&adj[(size_t)gr0 * NN + jc];
                aq[ks & 1][1] = *(const int2*)&adj[(size_t)gr1 * NN + jc];
                aq[ks & 1][2] = *(const int2*)&adj[(size_t)gr0 * NN + jc + 8];
                aq[ks & 1][3] = *(const int2*)&adj[(size_t)gr1 * NN + jc + 8];
            }

            if (fg == 0)
                mma_f16(dden, A, Bones[0], Bones[1]);

#pragma unroll
            for (int ng = 0; ng < 4; ng++) {
                uint32_t B[4];
                uint32_t bo = (uint32_t)(ks * 16 + (lane & 15)) * RB +
                              (F0 + ng * 16 + (lane >> 4) * 8) * 2;
                ldsm_x4_t(B, bbuf + bo);
                mma_f16(&acc[(ng * 2) * 4],     A, B[0], B[1]);
                mma_f16(&acc[(ng * 2 + 1) * 4], A, B[2], B[3]);
            }
        }
        CP_WAIT0();
        __syncthreads();
    }

    // ---- den writeout: F-group 0 only; den sits in output col 0 of the ones-mma ----
    if (fg == 0 && (lane & 3) == 0) {
        g_den[(size_t)jh * NN + gr0] = dden[0];
        g_den[(size_t)jh * NN + gr1] = dden[2];
    }

    // ---- numerator writeout ----
#pragma unroll
    for (int nb = 0; nb < 8; nb++) {
        const float* d = &acc[nb * 4];
        int col = F0 + nb * 8 + cq;
        size_t o0 = ((size_t)jh * NN + gr0) * FOUT + col;
        size_t o1 = ((size_t)jh * NN + gr1) * FOUT + col;
        *(float2*)&g_num[o0] = make_float2(d[0], d[1]);
        *(float2*)&g_num[o1] = make_float2(d[2], d[3]);
    }
}

// ---------------- Kernel 3: combine ----------------
__global__ __launch_bounds__(256) void k3_combine(float* __restrict__ out)
{
    int idx = blockIdx.x * 256 + threadIdx.x;
    int i = idx >> 5;
    float inv = 1.0f / (g_den[i] + g_den[NN + i]);
    float4 a = *(const float4*)&g_num[(size_t)idx * 4];
    float4 b = *(const float4*)&g_num[(size_t)NN * FOUT + (size_t)idx * 4];
    float4 o;
    o.x = (a.x + b.x) * inv; o.y = (a.y + b.y) * inv;
    o.z = (a.z + b.z) * inv; o.w = (a.w + b.w) * inv;
    *(float4*)&out[(size_t)idx * 4] = o;
}

// ---------------- launcher ----------------
extern "C" void kernel_launch(void* const* d_in, const int* in_sizes, int n_in,
                              void* d_out, int out_size)
{
    const float* h   = (const float*)d_in[0];
    const int*   adj = (const int*)  d_in[1];
    const float* W   = (const float*)d_in[2];
    const float* a   = (const float*)d_in[3];
    float* out = (float*)d_out;
    (void)in_sizes; (void)n_in; (void)out_size;

    cudaFuncSetAttribute(k1_gemm_s, cudaFuncAttributeMaxDynamicSharedMemorySize, K1_SMEM);
    cudaFuncSetAttribute(k2_attn,  cudaFuncAttributeMaxDynamicSharedMemorySize, K2_SMEM);

    k1_gemm_s<<<NN / 64, 512, K1_SMEM>>>(h, W, a);
    k2_attn<<<NN / 64, 512, K2_SMEM>>>(adj);
    k3_combine<<<NN * FOUT / 4 / 256, 256>>>(out);
}

// round 9
// speedup vs baseline: 1.9544x; 1.3588x over previous
#include <cuda_runtime.h>
#include <cuda_fp16.h>
#include <cstdint>

#define NN   8192
#define FIN  256
#define FOUT 128

// ---------------- device scratch ----------------
__device__ __align__(16) __half g_Wh[NN * FOUT];       // [j][f] fp16
__device__ __align__(16) float  g_num[4 * NN * FOUT];  // 4-way split-j partials
__device__ float  g_den[4 * NN];
__device__ __align__(16) float4 g_e1[NN];              // (e^s1, e^{0.2 s1}, s1, 0)
__device__ __align__(16) uint4  g_lut[NN / 2];         // per j-pair: {e2p2, e2n2, s22, 0} fp16x2

// ---------------- helpers ----------------
__device__ __forceinline__ uint32_t smem_u32(const void* p) {
    uint32_t a;
    asm("{ .reg .u64 t; cvta.to.shared.u64 t, %1; cvt.u32.u64 %0, t; }" : "=r"(a) : "l"(p));
    return a;
}
__device__ __forceinline__ void ldsm_x4(uint32_t* r, uint32_t addr) {
    asm volatile("ldmatrix.sync.aligned.m8n8.x4.shared.b16 {%0,%1,%2,%3}, [%4];"
                 : "=r"(r[0]), "=r"(r[1]), "=r"(r[2]), "=r"(r[3]) : "r"(addr));
}
__device__ __forceinline__ void ldsm_x4_t(uint32_t* r, uint32_t addr) {
    asm volatile("ldmatrix.sync.aligned.m8n8.x4.trans.shared.b16 {%0,%1,%2,%3}, [%4];"
                 : "=r"(r[0]), "=r"(r[1]), "=r"(r[2]), "=r"(r[3]) : "r"(addr));
}
__device__ __forceinline__ void mma_f16(float* d, const uint32_t* a, uint32_t b0, uint32_t b1) {
    asm volatile(
        "mma.sync.aligned.m16n8k16.row.col.f32.f16.f16.f32 "
        "{%0,%1,%2,%3}, {%4,%5,%6,%7}, {%8,%9}, {%0,%1,%2,%3};"
        : "+f"(d[0]), "+f"(d[1]), "+f"(d[2]), "+f"(d[3])
        : "r"(a[0]), "r"(a[1]), "r"(a[2]), "r"(a[3]), "r"(b0), "r"(b1));
}
__device__ __forceinline__ void cp_async16(uint32_t dst, const void* src) {
    asm volatile("cp.async.cg.shared.global [%0], [%1], 16;" :: "r"(dst), "l"(src));
}
#define CP_COMMIT() asm volatile("cp.async.commit_group;" ::: "memory")
#define CP_WAIT0()  asm volatile("cp.async.wait_group 0;" ::: "memory")
__device__ __forceinline__ uint32_t h2u(__half2 h) { return *(uint32_t*)&h; }
__device__ __forceinline__ uint32_t bcast_h2(float f) {
    __half2 v = __float2half2_rn(f);
    return *(uint32_t*)&v;
}
// premasked adj pair -> u32 lane mask
__device__ __forceinline__ uint32_t adj_mask(int2 a) {
    return (uint32_t)a.x * 0xFFFFu + (uint32_t)a.y * 0xFFFF0000u;
}
// A-frag half2 gen: p = am & (s2>=-s1 ? e1p*e2p : e1n*e2n), all fixed-lat pipes.
__device__ __forceinline__ uint32_t genA(uint32_t e2p2, uint32_t e2n2, uint32_t s22,
                                         uint32_t e1p, uint32_t e1n, uint32_t ns1,
                                         uint32_t am) {
    uint32_t pp, pn, mk;
    asm("mul.f16x2 %0, %1, %2;" : "=r"(pp) : "r"(e1p), "r"(e2p2));
    asm("mul.f16x2 %0, %1, %2;" : "=r"(pn) : "r"(e1n), "r"(e2n2));
    asm("set.ge.u32.f16x2 %0, %1, %2;" : "=r"(mk) : "r"(s22), "r"(ns1));
    return (((pp & mk) | (pn & ~mk)) & am);
}

// ---------------- Kernel 1 (unchanged from R8) ----------------
#define R1H 528
#define R1W 272
#define HH_OFF 0
#define HL_OFF (64 * R1H)
#define WH_OFF (2 * 64 * R1H)
#define WL_OFF (WH_OFF + 256 * R1W)
#define K1_SMEM (WL_OFF + 256 * R1W)
#define AVEC_OFF (64 * 132 * 4)

__global__ __launch_bounds__(512, 1) void k1_gemm_s(
    const float* __restrict__ h, const float* __restrict__ W,
    const float* __restrict__ a)
{
    extern __shared__ char base[];
    const uint32_t sb = smem_u32(base);
    const int t = threadIdx.x, lane = t & 31, w = t >> 5;
    const int row0 = blockIdx.x * 64;

#pragma unroll
    for (int p = 0; p < 8; p++) {
        int id = t + p * 512;
        int r = id >> 6, c4 = id & 63;
        float4 v = *(const float4*)&h[(size_t)(row0 + r) * FIN + c4 * 4];
        __half x0 = __float2half_rn(v.x), x1 = __float2half_rn(v.y);
        __half x2 = __float2half_rn(v.z), x3 = __float2half_rn(v.w);
        __half2 hp0, hp1, lp0, lp1;
        hp0.x = x0; hp0.y = x1; hp1.x = x2; hp1.y = x3;
        lp0.x = __float2half_rn(v.x - __half2float(x0));
        lp0.y = __float2half_rn(v.y - __half2float(x1));
        lp1.x = __float2half_rn(v.z - __half2float(x2));
        lp1.y = __float2half_rn(v.w - __half2float(x3));
        uint32_t off = (uint32_t)r * R1H + c4 * 8;
        *(uint2*)(base + HH_OFF + off) = make_uint2(h2u(hp0), h2u(hp1));
        *(uint2*)(base + HL_OFF + off) = make_uint2(h2u(lp0), h2u(lp1));
    }
#pragma unroll
    for (int p = 0; p < 16; p++) {
        int id = t + p * 512;
        int k = id >> 5, f4 = id & 31;
        float4 v = *(const float4*)&W[(size_t)k * FOUT + f4 * 4];
        __half x0 = __float2half_rn(v.x), x1 = __float2half_rn(v.y);
        __half x2 = __float2half_rn(v.z), x3 = __float2half_rn(v.w);
        __half2 hp0, hp1, lp0, lp1;
        hp0.x = x0; hp0.y = x1; hp1.x = x2; hp1.y = x3;
        lp0.x = __float2half_rn(v.x - __half2float(x0));
        lp0.y = __float2half_rn(v.y - __half2float(x1));
        lp1.x = __float2half_rn(v.z - __half2float(x2));
        lp1.y = __float2half_rn(v.w - __half2float(x3));
        uint32_t off = (uint32_t)k * R1W + f4 * 8;
        *(uint2*)(base + WH_OFF + off) = make_uint2(h2u(hp0), h2u(hp1));
        *(uint2*)(base + WL_OFF + off) = make_uint2(h2u(lp0), h2u(lp1));
    }
    __syncthreads();

    const int mrow0 = (w & 3) * 16;
    const int ncol0 = (w >> 2) * 32;
    float acc[16];
#pragma unroll
    for (int q = 0; q < 16; q++) acc[q] = 0.0f;

    const uint32_t aH = sb + HH_OFF + (uint32_t)(mrow0 + (lane & 15)) * R1H + (lane >> 4) * 16;
    const uint32_t aL = aH + (HL_OFF - HH_OFF);

#pragma unroll
    for (int ks = 0; ks < 16; ks++) {
        uint32_t Ah[4], Al[4];
        ldsm_x4(Ah, aH + ks * 32);
        ldsm_x4(Al, aL + ks * 32);
#pragma unroll
        for (int ng = 0; ng < 2; ng++) {
            uint32_t bo = (uint32_t)(ks * 16 + (lane & 15)) * R1W +
                          (ncol0 + ng * 16 + (lane >> 4) * 8) * 2;
            uint32_t Bh[4], Bl[4];
            ldsm_x4_t(Bh, sb + WH_OFF + bo);
            ldsm_x4_t(Bl, sb + WL_OFF + bo);
#pragma unroll
            for (int s = 0; s < 2; s++) {
                float* d = &acc[(ng * 2 + s) * 4];
                mma_f16(d, Ah, Bh[s * 2], Bh[s * 2 + 1]);
                mma_f16(d, Ah, Bl[s * 2], Bl[s * 2 + 1]);
                mma_f16(d, Al, Bh[s * 2], Bh[s * 2 + 1]);
            }
        }
    }
    __syncthreads();

    float* stage = (float*)base;
    float* a_s   = (float*)(base + AVEC_OFF);
#pragma unroll
    for (int nb = 0; nb < 4; nb++) {
        const float* d = &acc[nb * 4];
        int row = mrow0 + (lane >> 2);
        int col = ncol0 + (nb >> 1) * 16 + (nb & 1) * 8 + (lane & 3) * 2;
        stage[row * 132 + col]     = d[0];
        stage[row * 132 + col + 1] = d[1];
        stage[(row + 8) * 132 + col]     = d[2];
        stage[(row + 8) * 132 + col + 1] = d[3];
    }
    if (t < 256) a_s[t] = a[t];
    __syncthreads();

    if (t < 64) {
        float p1 = 0.f, p2 = 0.f;
#pragma unroll 8
        for (int c = 0; c < 128; c++) {
            float v = stage[t * 132 + c];
            p1 = fmaf(v, a_s[c], p1);
            p2 = fmaf(v, a_s[128 + c], p2);
        }
        g_e1[row0 + t] = make_float4(__expf(p1), __expf(0.2f * p1), p1, 0.0f);
        float e2p = __expf(p2), e2n = __expf(0.2f * p2);
        float e2p_n = __shfl_down_sync(0xffffffffu, e2p, 1);
        float e2n_n = __shfl_down_sync(0xffffffffu, e2n, 1);
        float s2_n  = __shfl_down_sync(0xffffffffu, p2, 1);
        if ((t & 1) == 0) {
            __half2 a0 = __floats2half2_rn(e2p, e2p_n);
            __half2 b0 = __floats2half2_rn(e2n, e2n_n);
            __half2 c0 = __floats2half2_rn(p2, s2_n);
            uint4 e;
            e.x = h2u(a0); e.y = h2u(b0); e.z = h2u(c0); e.w = 0;
            g_lut[(row0 + t) >> 1] = e;
        }
    }
    {
        int row = t >> 3;
        int f0  = (t & 7) * 16;
#pragma unroll
        for (int q = 0; q < 8; q++) {
            __half2 hp;
            hp.x = __float2half_rn(stage[row * 132 + f0 + q * 2]);
            hp.y = __float2half_rn(stage[row * 132 + f0 + q * 2 + 1]);
            *(__half2*)&g_Wh[(size_t)(row0 + row) * FOUT + f0 + q * 2] = hp;
        }
    }
}

// ---------------- Kernel 2 ----------------
// 128 CTAs = 32 i-tiles (256 rows) x 4 j-quarters (2048). 512 thr, 16 warps.
// Warp = m16 x n128 -> no duplicated genA/adj/LUT work. 16 j-tiles of 128.
#define RB     272
#define BTILE  (128 * RB)
#define LUT_OFF (2 * BTILE)
#define K2_SMEM (LUT_OFF + 2048 + 256)

__global__ __launch_bounds__(512, 1) void k2_attn(const int* __restrict__ adj)
{
    extern __shared__ char base[];
    const uint32_t sb = smem_u32(base);

    const int t = threadIdx.x, lane = t & 31, w = t >> 5;
    const int i0   = (blockIdx.x >> 2) * 256;
    const int q    = blockIdx.x & 3;
    const int jbeg = q * 2048;

    const int mrow0 = w * 16;            // unique m-strip per warp
    const int cq    = (lane & 3) * 2;

    const int gr0 = i0 + mrow0 + (lane >> 2);
    const int gr1 = gr0 + 8;
    const float4 E0 = g_e1[gr0];
    const float4 E1 = g_e1[gr1];
    const uint32_t e1p0 = bcast_h2(E0.x), e1n0 = bcast_h2(E0.y), ns10 = bcast_h2(-E0.z);
    const uint32_t e1p1 = bcast_h2(E1.x), e1n1 = bcast_h2(E1.y), ns11 = bcast_h2(-E1.z);

    float acc[64];
#pragma unroll
    for (int z = 0; z < 64; z++) acc[z] = 0.0f;
    float dden[4] = {0.f, 0.f, 0.f, 0.f};

    const int bj = t >> 4;
    const int bc = t & 15;

    // ones-pad in both buffers (bytes 256..271 of each j-row)
    if (t < 128) {
        uint4 z = make_uint4(0x00003C00u, 0u, 0u, 0u);
        *(uint4*)(base + (uint32_t)t * RB + 256) = z;
        *(uint4*)(base + BTILE + (uint32_t)t * RB + 256) = z;
    }

    // ---- prologue: stage tile 0, prime adj ring (premasked) ----
    {
#pragma unroll
        for (int p = 0; p < 4; p++) {
            int j = bj + p * 32;
            cp_async16(sb + (uint32_t)j * RB + bc * 16,
                       &g_Wh[(size_t)(jbeg + j) * FOUT + bc * 8]);
        }
        if (t < 64)
            cp_async16(sb + LUT_OFF + t * 16, &g_lut[(jbeg >> 1) + t]);
        CP_COMMIT();
    }
    uint32_t aq[2][4];
#pragma unroll
    for (int s = 0; s < 2; s++) {
        int jc = jbeg + s * 16 + cq;
        aq[s][0] = adj_mask(*(const int2*)&adj[(size_t)gr0 * NN + jc]);
        aq[s][1] = adj_mask(*(const int2*)&adj[(size_t)gr1 * NN + jc]);
        aq[s][2] = adj_mask(*(const int2*)&adj[(size_t)gr0 * NN + jc + 8]);
        aq[s][3] = adj_mask(*(const int2*)&adj[(size_t)gr1 * NN + jc + 8]);
    }
    CP_WAIT0();
    __syncthreads();

    // hoisted constant ones-column B fragment
    uint32_t Bones[4];
    ldsm_x4_t(Bones, sb + (uint32_t)(lane & 15) * RB + 256 + (uint32_t)(lane >> 4) * 16);

    // ---- main loop: 16 tiles of 128 j ----
    for (int it = 0; it < 16; it++) {
        const uint32_t bbuf = sb + (uint32_t)(it & 1) * BTILE;
        const uint32_t loff = LUT_OFF + (uint32_t)(it & 1) * 1024;

        if (it < 15) {
            const int j0n = jbeg + (it + 1) * 128;
            const uint32_t nb = sb + (uint32_t)((it + 1) & 1) * BTILE;
#pragma unroll
            for (int p = 0; p < 4; p++) {
                int j = bj + p * 32;
                cp_async16(nb + (uint32_t)j * RB + bc * 16,
                           &g_Wh[(size_t)(j0n + j) * FOUT + bc * 8]);
            }
            if (t < 64)
                cp_async16(sb + LUT_OFF + (uint32_t)((it + 1) & 1) * 1024 + t * 16,
                           &g_lut[(j0n >> 1) + t]);
            CP_COMMIT();
        }

#pragma unroll
        for (int ks = 0; ks < 8; ks++) {
            uint4 L0 = *(const uint4*)(base + loff + (ks * 8 + (lane & 3)) * 16);
            uint4 L1 = *(const uint4*)(base + loff + (ks * 8 + (lane & 3) + 4) * 16);

            uint32_t A[4];
            A[0] = genA(L0.x, L0.y, L0.z, e1p0, e1n0, ns10, aq[ks & 1][0]);
            A[1] = genA(L0.x, L0.y, L0.z, e1p1, e1n1, ns11, aq[ks & 1][1]);
            A[2] = genA(L1.x, L1.y, L1.z, e1p0, e1n0, ns10, aq[ks & 1][2]);
            A[3] = genA(L1.x, L1.y, L1.z, e1p1, e1n1, ns11, aq[ks & 1][3]);

            // refill adj ring for ksg+2
            {
                int ksg2 = it * 8 + ks + 2;
                if (ksg2 > 127) ksg2 = 127;
                int jc = jbeg + (ksg2 >> 3) * 128 + (ksg2 & 7) * 16 + cq;
                aq[ks & 1][0] = adj_mask(*(const int2*)&adj[(size_t)gr0 * NN + jc]);
                aq[ks & 1][1] = adj_mask(*(const int2*)&adj[(size_t)gr1 * NN + jc]);
                aq[ks & 1][2] = adj_mask(*(const int2*)&adj[(size_t)gr0 * NN + jc + 8]);
                aq[ks & 1][3] = adj_mask(*(const int2*)&adj[(size_t)gr1 * NN + jc + 8]);
            }

            mma_f16(dden, A, Bones[0], Bones[1]);

#pragma unroll
            for (int ng = 0; ng < 8; ng++) {
                uint32_t B[4];
                uint32_t bo = (uint32_t)(ks * 16 + (lane & 15)) * RB +
                              (ng * 16 + (lane >> 4) * 8) * 2;
                ldsm_x4_t(B, bbuf + bo);
                mma_f16(&acc[(ng * 2) * 4],     A, B[0], B[1]);
                mma_f16(&acc[(ng * 2 + 1) * 4], A, B[2], B[3]);
            }
        }
        CP_WAIT0();
        __syncthreads();
    }

    // ---- den writeout (col 0 of ones-mma) ----
    if ((lane & 3) == 0) {
        g_den[(size_t)q * NN + gr0] = dden[0];
        g_den[(size_t)q * NN + gr1] = dden[2];
    }

    // ---- numerator writeout ----
#pragma unroll
    for (int nb = 0; nb < 16; nb++) {
        const float* d = &acc[nb * 4];
        int col = nb * 8 + cq;
        size_t o0 = ((size_t)q * NN + gr0) * FOUT + col;
        size_t o1 = ((size_t)q * NN + gr1) * FOUT + col;
        *(float2*)&g_num[o0] = make_float2(d[0], d[1]);
        *(float2*)&g_num[o1] = make_float2(d[2], d[3]);
    }
}

// ---------------- Kernel 3: combine 4 partials ----------------
__global__ __launch_bounds__(256) void k3_combine(float* __restrict__ out)
{
    int idx = blockIdx.x * 256 + threadIdx.x;       // float4 index
    int i = idx >> 5;
    float inv = 1.0f / ((g_den[i] + g_den[NN + i]) +
                        (g_den[2 * NN + i] + g_den[3 * NN + i]));
    const size_t STR = (size_t)NN * FOUT;
    float4 a0 = *(const float4*)&g_num[(size_t)idx * 4];
    float4 a1 = *(const float4*)&g_num[STR + (size_t)idx * 4];
    float4 a2 = *(const float4*)&g_num[2 * STR + (size_t)idx * 4];
    float4 a3 = *(const float4*)&g_num[3 * STR + (size_t)idx * 4];
    float4 o;
    o.x = ((a0.x + a1.x) + (a2.x + a3.x)) * inv;
    o.y = ((a0.y + a1.y) + (a2.y + a3.y)) * inv;
    o.z = ((a0.z + a1.z) + (a2.z + a3.z)) * inv;
    o.w = ((a0.w + a1.w) + (a2.w + a3.w)) * inv;
    *(float4*)&out[(size_t)idx * 4] = o;
}

// ---------------- launcher ----------------
extern "C" void kernel_launch(void* const* d_in, const int* in_sizes, int n_in,
                              void* d_out, int out_size)
{
    const float* h   = (const float*)d_in[0];
    const int*   adj = (const int*)  d_in[1];
    const float* W   = (const float*)d_in[2];
    const float* a   = (const float*)d_in[3];
    float* out = (float*)d_out;
    (void)in_sizes; (void)n_in; (void)out_size;

    cudaFuncSetAttribute(k1_gemm_s, cudaFuncAttributeMaxDynamicSharedMemorySize, K1_SMEM);
    cudaFuncSetAttribute(k2_attn,  cudaFuncAttributeMaxDynamicSharedMemorySize, K2_SMEM);

    k1_gemm_s<<<NN / 64, 512, K1_SMEM>>>(h, W, a);
    k2_attn<<<(NN / 256) * 4, 512, K2_SMEM>>>(adj);
    k3_combine<<<NN * FOUT / 4 / 256, 256>>>(out);
}